// round 2
// baseline (speedup 1.0000x reference)
#include <cuda_runtime.h>

#define SEQ    512
#define BATCH  1024
#define NTAG   64
#define NEGINF -10000.0f

// g_E2[h*1024 + k*32 + l] = packed f32x2 ( exp(T[l+32h][2k]), exp(T[l+32h][2k+1]) )
__device__ __align__(16) unsigned long long g_E2[2 * 32 * 32];
__device__ float g_K;   // log(max_j sum_i exp(T[j,i])) + margin

__device__ __forceinline__ float ex2f_(float x) {
    float y; asm("ex2.approx.ftz.f32 %0, %1;" : "=f"(y) : "f"(x)); return y;
}
__device__ __forceinline__ float lg2f_(float x) {
    float y; asm("lg2.approx.ftz.f32 %0, %1;" : "=f"(y) : "f"(x)); return y;
}
__device__ __forceinline__ unsigned long long fma2_(unsigned long long a,
                                                    unsigned long long b,
                                                    unsigned long long c) {
    unsigned long long d;
    asm("fma.rn.f32x2 %0, %1, %2, %3;" : "=l"(d) : "l"(a), "l"(b), "l"(c));
    return d;
}
__device__ __forceinline__ unsigned long long add2_(unsigned long long a,
                                                    unsigned long long b) {
    unsigned long long d;
    asm("add.rn.f32x2 %0, %1, %2;" : "=l"(d) : "l"(a), "l"(b));
    return d;
}
__device__ __forceinline__ void unpack_(unsigned long long v, float& x, float& y) {
    asm("mov.b64 {%0, %1}, %2;" : "=f"(x), "=f"(y) : "l"(v));
}
__device__ __forceinline__ float wmax_(float v) {
#pragma unroll
    for (int d = 16; d; d >>= 1)
        v = fmaxf(v, __shfl_xor_sync(0xffffffffu, v, d));
    return v;
}

// E = exp(transition), packed in i-pairs, lane-major for coalesced register fill.
__global__ void crf_setup(const float* __restrict__ trans) {
    int t = blockIdx.x * blockDim.x + threadIdx.x;
    if (t >= 2048) return;
    int l = t & 31, k = (t >> 5) & 31, h = t >> 10;
    int j = l + 32 * h;
    float e0 = __expf(trans[j * NTAG + 2 * k]);      // exp(-10000) -> 0 (START row)
    float e1 = __expf(trans[j * NTAG + 2 * k + 1]);
    unsigned long long u;
    asm("mov.b64 %0, {%1, %2};" : "=l"(u) : "f"(e0), "f"(e1));
    g_E2[h * 1024 + k * 32 + l] = u;
}

// K = log(max_j sum_i exp(T[j,i])) + safety margin
__global__ void crf_bound(const float* __restrict__ trans) {
    __shared__ float rs[NTAG];
    int j = threadIdx.x;
    float s = 0.0f;
    for (int i = 0; i < NTAG; ++i) s += __expf(trans[j * NTAG + i]);
    rs[j] = s;
    __syncthreads();
    if (j == 0) {
        float m = rs[0];
        for (int i = 1; i < NTAG; ++i) m = fmaxf(m, rs[i]);
        g_K = __logf(fmaxf(m, 1e-30f)) + 1.0f;
    }
}

// One warp per batch. Lane l owns tags (l, l+32); E rows resident in 128 regs
// as i-pair f32x2. Normalizer mu is a 2-step-lagged upper bound so the warp-max
// shuffle chain is OFF the per-step critical path.
__global__ void __launch_bounds__(256, 1)
crf_main(const float* __restrict__ feats,
         const float* __restrict__ mask,
         const float* __restrict__ trans,
         float* __restrict__ out) {
    const int lane = threadIdx.x & 31;
    const int w    = threadIdx.x >> 5;
    const int b    = blockIdx.x * 8 + w;

    __shared__ __align__(16) float pbuf[8][2][NTAG];

    unsigned long long EA[32], EB[32];
#pragma unroll
    for (int k = 0; k < 32; ++k) {
        EA[k] = g_E2[k * 32 + lane];
        EB[k] = g_E2[1024 + k * 32 + lane];
    }
    const float Kv   = g_K;
    const float t_lo = trans[1 * NTAG + lane];       // END row
    const float t_hi = trans[1 * NTAG + 32 + lane];

    float a_lo = (lane == 0) ? 0.0f : NEGINF;        // START_IDX = 0
    float a_hi = NEGINF;

    const float* fbase = feats + (size_t)b * NTAG + lane;

    // prefetch depth 2 (offsets: step s -> s << 16 floats, since BATCH*NTAG = 65536)
    float f_lo[2], f_hi[2], mk[2];
    f_lo[0] = fbase[0];
    f_hi[0] = fbase[32];
    f_lo[1] = fbase[(size_t)1 << 16];
    f_hi[1] = fbase[((size_t)1 << 16) + 32];
    mk[0] = mask[b];
    mk[1] = mask[BATCH + b];

    const float L2E = 1.4426950408889634f;
    const float LN2 = 0.6931471805599453f;

    // normalizer pipeline: mu_c bounds max(alpha before current step)
    const float inc0 = fmaxf(wmax_(fmaxf(f_lo[0], f_hi[0])) + Kv, 0.0f);
    float incA = fmaxf(wmax_(fmaxf(f_lo[1], f_hi[1])) + Kv, 0.0f);   // inc_{s+1}
    float mu_c = 0.0f;      // max(alpha_0) = 0 exactly
    float mu_n = inc0;      // bound for step 1

#pragma unroll 2
    for (int s = 0; s < SEQ; ++s) {
        const int ph = s & 1;
        if (mk[ph] == 0.0f) break;                   // mask is monotone 1..1 0..0
        const float fc_lo = f_lo[ph];
        const float fc_hi = f_hi[ph];

        // p = exp(alpha - mu_c); mu_c known ahead of time (off critical path)
        const float c = -mu_c * L2E;
        pbuf[w][ph][lane]      = ex2f_(fmaf(a_lo, L2E, c));
        pbuf[w][ph][lane + 32] = ex2f_(fmaf(a_hi, L2E, c));
        __syncwarp();

        // prefetch step s+2 (clamped; redundant tail load harmless)
        const int sp = (s + 2 < SEQ) ? s + 2 : SEQ - 1;
        const float nf_lo = fbase[(size_t)sp << 16];
        const float nf_hi = fbase[((size_t)sp << 16) + 32];
        const float nmk   = mask[((size_t)sp << 10) + b];

        // S_j = sum_i E[j,i] * p_i : 16 LDS.128 (broadcast) + 64 FFMA2
        const ulonglong2* pb =
            reinterpret_cast<const ulonglong2*>(&pbuf[w][ph][0]);
        unsigned long long aA0 = 0ull, aA1 = 0ull, aB0 = 0ull, aB1 = 0ull;
#pragma unroll
        for (int k = 0; k < 16; ++k) {
            ulonglong2 q = pb[k];
            aA0 = fma2_(EA[2 * k],     q.x, aA0);
            aA1 = fma2_(EA[2 * k + 1], q.y, aA1);
            aB0 = fma2_(EB[2 * k],     q.x, aB0);
            aB1 = fma2_(EB[2 * k + 1], q.y, aB1);
        }
        float sA0, sA1, sB0, sB1;
        unpack_(add2_(aA0, aA1), sA0, sA1);
        unpack_(add2_(aB0, aB1), sB0, sB1);
        const float S_lo = sA0 + sA1;
        const float S_hi = sB0 + sB1;

        // alpha' = mu_c + feat + log S  (exact for any mu_c; floor kills log(0)
        // on the START row whose E-row is identically zero)
        a_lo = fmaf(lg2f_(fmaxf(S_lo, 1e-37f)), LN2, mu_c + fc_lo);
        a_hi = fmaf(lg2f_(fmaxf(S_hi, 1e-37f)), LN2, mu_c + fc_hi);

        // off-path: anchor normalizer for step s+2
        const float M   = wmax_(fmaxf(a_lo, a_hi));          // exact max(alpha_s)
        const float inN = fmaxf(wmax_(fmaxf(nf_lo, nf_hi)) + Kv, 0.0f); // inc_{s+2}
        mu_c = mu_n;
        mu_n = M + incA;                                     // bound for step s+2
        incA = inN;

        f_lo[ph] = nf_lo;
        f_hi[ph] = nf_hi;
        mk[ph]   = nmk;
    }

    // out[b] = LSE_j( alpha[j] + T[END][j] )
    const float x_lo = a_lo + t_lo;
    const float x_hi = a_hi + t_hi;
    const float m = wmax_(fmaxf(x_lo, x_hi));
    const float c = -m * L2E;
    float ssum = ex2f_(fmaf(x_lo, L2E, c)) + ex2f_(fmaf(x_hi, L2E, c));
#pragma unroll
    for (int d = 16; d; d >>= 1)
        ssum += __shfl_xor_sync(0xffffffffu, ssum, d);
    if (lane == 0) out[b] = fmaf(lg2f_(ssum), LN2, m);
}

extern "C" void kernel_launch(void* const* d_in, const int* in_sizes, int n_in,
                              void* d_out, int out_size) {
    const float* feats = nullptr;
    const float* maskp = nullptr;
    const float* trans = nullptr;
    for (int i = 0; i < n_in; ++i) {
        if (in_sizes[i] == SEQ * BATCH * NTAG)      feats = (const float*)d_in[i];
        else if (in_sizes[i] == SEQ * BATCH)        maskp = (const float*)d_in[i];
        else if (in_sizes[i] == NTAG * NTAG)        trans = (const float*)d_in[i];
    }
    crf_setup<<<8, 256>>>(trans);
    crf_bound<<<1, 64>>>(trans);
    crf_main<<<BATCH / 8, 256>>>(feats, maskp, trans, (float*)d_out);
}

// round 3
// speedup vs baseline: 1.7362x; 1.7362x over previous
#include <cuda_runtime.h>
#include <cstdint>

#define SEQ    512
#define BATCH  1024
#define NTAG   64
#define NEGINF -10000.0f
#define DEPTH  8

// g_E2[h*1024 + k*32 + l] = packed f32x2 ( exp(T[l+32h][2k]), exp(T[l+32h][2k+1]) )
__device__ __align__(16) unsigned long long g_E2[2 * 32 * 32];
__device__ int g_len[BATCH];

__device__ __forceinline__ float ex2f_(float x) {
    float y; asm("ex2.approx.ftz.f32 %0, %1;" : "=f"(y) : "f"(x)); return y;
}
__device__ __forceinline__ float lg2f_(float x) {
    float y; asm("lg2.approx.ftz.f32 %0, %1;" : "=f"(y) : "f"(x)); return y;
}
__device__ __forceinline__ unsigned long long fma2_(unsigned long long a,
                                                    unsigned long long b,
                                                    unsigned long long c) {
    unsigned long long d;
    asm("fma.rn.f32x2 %0, %1, %2, %3;" : "=l"(d) : "l"(a), "l"(b), "l"(c));
    return d;
}
__device__ __forceinline__ unsigned long long add2_(unsigned long long a,
                                                    unsigned long long b) {
    unsigned long long d;
    asm("add.rn.f32x2 %0, %1, %2;" : "=l"(d) : "l"(a), "l"(b));
    return d;
}
__device__ __forceinline__ void unpack_(unsigned long long v, float& x, float& y) {
    asm("mov.b64 {%0, %1}, %2;" : "=f"(x), "=f"(y) : "l"(v));
}
__device__ __forceinline__ float wmax_(float v) {
#pragma unroll
    for (int d = 16; d; d >>= 1)
        v = fmaxf(v, __shfl_xor_sync(0xffffffffu, v, d));
    return v;
}
__device__ __forceinline__ uint32_t smem_u32_(const void* p) {
    uint32_t a;
    asm("{ .reg .u64 t; cvta.to.shared.u64 t, %1; cvt.u32.u64 %0, t; }"
        : "=r"(a) : "l"(p));
    return a;
}
__device__ __forceinline__ void cpa8_(uint32_t dst, const float* src) {
    asm volatile("cp.async.ca.shared.global [%0], [%1], 8;" :: "r"(dst), "l"(src));
}
__device__ __forceinline__ void cpa_commit_() {
    asm volatile("cp.async.commit_group;" ::: "memory");
}
__device__ __forceinline__ void cpa_wait7_() {
    asm volatile("cp.async.wait_group %0;" :: "n"(DEPTH - 1) : "memory");
}

// One setup launch: blocks 0..31 compute len[b] (mask is monotone 1..1 0..0),
// blocks 32..39 build E = exp(transition) packed in i-pairs, lane-major.
__global__ void crf_prep(const float* __restrict__ trans,
                         const float* __restrict__ mask) {
    if (blockIdx.x < 32) {
        const int l = threadIdx.x & 31, c = threadIdx.x >> 5;
        const int b = blockIdx.x * 32 + l;
        float s = 0.0f;
#pragma unroll
        for (int i = 0; i < 64; ++i)
            s += mask[(size_t)(c * 64 + i) * BATCH + b];
        __shared__ float red[8][32];
        red[c][l] = s;
        __syncthreads();
        if (c == 0) {
            float t = 0.0f;
#pragma unroll
            for (int k = 0; k < 8; ++k) t += red[k][l];
            g_len[b] = (int)(t + 0.5f);
        }
    } else {
        const int t = (blockIdx.x - 32) * 256 + threadIdx.x;
        const int l = t & 31, k = (t >> 5) & 31, h = t >> 10;
        const int j = l + 32 * h;
        const float e0 = __expf(trans[j * NTAG + 2 * k]);   // exp(-1e4) -> 0
        const float e1 = __expf(trans[j * NTAG + 2 * k + 1]);
        unsigned long long u;
        asm("mov.b64 %0, {%1, %2};" : "=l"(u) : "f"(e0), "f"(e1));
        g_E2[h * 1024 + k * 32 + l] = u;
    }
}

// One warp = one CTA = one batch (grid 1024 -> 6-7 warps on every SM).
// feats streamed through a depth-8 cp.async ring; counted loop (no mask);
// normalizer mu_{s+1} = M_{s-1} + inc_s keeps both SHFL chains off the
// per-step critical path while remaining an exact upper bound.
__global__ void __launch_bounds__(32)
crf_main(const float* __restrict__ feats,
         const float* __restrict__ trans,
         float* __restrict__ out) {
    const int lane = threadIdx.x;
    const int b    = blockIdx.x;

    __shared__ __align__(16) float ring[DEPTH][NTAG];   // 2 KB
    __shared__ __align__(16) float pbuf[2][NTAG];       // 512 B

    unsigned long long EA[32], EB[32];
#pragma unroll
    for (int k = 0; k < 32; ++k) {
        EA[k] = g_E2[k * 32 + lane];
        EB[k] = g_E2[1024 + k * 32 + lane];
    }

    // Kv = log(max_j sum_i E[j,i]) + margin, straight from resident E regs.
    {
        unsigned long long sa = 0ull, sb = 0ull;
#pragma unroll
        for (int k = 0; k < 32; ++k) { sa = add2_(sa, EA[k]); sb = add2_(sb, EB[k]); }
        float a0, a1, b0, b1;
        unpack_(sa, a0, a1); unpack_(sb, b0, b1);
        float rs = fmaxf(a0 + a1, b0 + b1);
        rs = wmax_(rs);
        // stash in pbuf[0][0] slot? no — keep in register below
        const float LN2 = 0.6931471805599453f;
        rs = fmaxf(rs, 1e-30f);
        // Kv computed below via lg2
        pbuf[0][lane] = rs; // dummy to keep compiler honest? not needed
        (void)LN2;
    }
    const float LN2 = 0.6931471805599453f;
    const float L2E = 1.4426950408889634f;
    float Kv;
    {
        unsigned long long sa = 0ull, sb = 0ull;
#pragma unroll
        for (int k = 0; k < 32; ++k) { sa = add2_(sa, EA[k]); sb = add2_(sb, EB[k]); }
        float a0, a1, b0, b1;
        unpack_(sa, a0, a1); unpack_(sb, b0, b1);
        float rs = wmax_(fmaxf(a0 + a1, b0 + b1));
        Kv = fmaf(lg2f_(fmaxf(rs, 1e-30f)), LN2, 1.0f);
    }

    const float t_lo = trans[1 * NTAG + lane];       // END row
    const float t_hi = trans[1 * NTAG + 32 + lane];
    const int   len  = g_len[b];

    float a_lo = (lane == 0) ? 0.0f : NEGINF;        // START_IDX = 0
    float a_hi = NEGINF;

    const float* fbase = feats + (size_t)b * NTAG;   // step s at +s*65536
    const uint32_t ring_u = smem_u32_(&ring[0][0]);
    const uint32_t dst_ln = ring_u + lane * 8;

    // prologue: issue steps 0..DEPTH-2
#pragma unroll
    for (int t = 0; t < DEPTH - 1; ++t) {
        cpa8_(dst_ln + (t << 8), fbase + ((size_t)t << 16) + lane * 2);
        cpa_commit_();
    }

    float mu_c   = 0.0f;   // exact max(alpha_init)
    float M_prev = 0.0f;   // M_{s-1}, starts as M_{-1} = max(alpha_init)

#pragma unroll 2
    for (int s = 0; s < len; ++s) {
        const int ph = s & 1;

        // p = exp(alpha - mu_c); mu_c ready since previous iteration
        const float c = -mu_c * L2E;
        pbuf[ph][lane]      = ex2f_(fmaf(a_lo, L2E, c));
        pbuf[ph][lane + 32] = ex2f_(fmaf(a_hi, L2E, c));

        // stream: issue step s+DEPTH-1 (clamped; redundant dup writes of the
        // final step are byte-identical, benign), retire step s
        int sp = s + DEPTH - 1;
        if (sp > SEQ - 1) sp = SEQ - 1;
        cpa8_(dst_ln + ((sp & (DEPTH - 1)) << 8),
              fbase + ((size_t)sp << 16) + lane * 2);
        cpa_commit_();
        cpa_wait7_();
        __syncwarp();

        const float fc_lo = ring[s & (DEPTH - 1)][lane];
        const float fc_hi = ring[s & (DEPTH - 1)][lane + 32];

        // S_j = sum_i E[j,i] * p_i : 16 LDS.128 broadcast + 64 FFMA2
        const ulonglong2* pb = reinterpret_cast<const ulonglong2*>(&pbuf[ph][0]);
        unsigned long long aA0 = 0ull, aA1 = 0ull, aB0 = 0ull, aB1 = 0ull;
#pragma unroll
        for (int k = 0; k < 16; ++k) {
            ulonglong2 q = pb[k];
            aA0 = fma2_(EA[2 * k],     q.x, aA0);
            aA1 = fma2_(EA[2 * k + 1], q.y, aA1);
            aB0 = fma2_(EB[2 * k],     q.x, aB0);
            aB1 = fma2_(EB[2 * k + 1], q.y, aB1);
        }
        float sA0, sA1, sB0, sB1;
        unpack_(add2_(aA0, aA1), sA0, sA1);
        unpack_(add2_(aB0, aB1), sB0, sB1);
        const float S_lo = sA0 + sA1;
        const float S_hi = sB0 + sB1;

        // alpha' = mu_c + feat + log S (exact for any mu_c; floor kills the
        // all-zero START row's log(0))
        const float base = mu_c;
        a_lo = fmaf(lg2f_(fmaxf(S_lo, 1e-37f)), LN2, base + fc_lo);
        a_hi = fmaf(lg2f_(fmaxf(S_hi, 1e-37f)), LN2, base + fc_hi);

        // normalizer pipeline (off critical path):
        // mu_{s+1} = M_{s-1} + inc_s,  inc_s = max(wmax(f_s)+K, 0)
        const float inc_s = fmaxf(wmax_(fmaxf(fc_lo, fc_hi)) + Kv, 0.0f);
        mu_c   = M_prev + inc_s;
        M_prev = wmax_(fmaxf(a_lo, a_hi));   // exact max(alpha_s), for s+2
    }

    // out[b] = LSE_j( alpha[j] + T[END][j] )
    const float x_lo = a_lo + t_lo;
    const float x_hi = a_hi + t_hi;
    const float m = wmax_(fmaxf(x_lo, x_hi));
    const float c = -m * L2E;
    float ssum = ex2f_(fmaf(x_lo, L2E, c)) + ex2f_(fmaf(x_hi, L2E, c));
#pragma unroll
    for (int d = 16; d; d >>= 1)
        ssum += __shfl_xor_sync(0xffffffffu, ssum, d);
    if (lane == 0) out[b] = fmaf(lg2f_(ssum), LN2, m);
}

extern "C" void kernel_launch(void* const* d_in, const int* in_sizes, int n_in,
                              void* d_out, int out_size) {
    const float* feats = nullptr;
    const float* maskp = nullptr;
    const float* trans = nullptr;
    for (int i = 0; i < n_in; ++i) {
        if (in_sizes[i] == SEQ * BATCH * NTAG)      feats = (const float*)d_in[i];
        else if (in_sizes[i] == SEQ * BATCH)        maskp = (const float*)d_in[i];
        else if (in_sizes[i] == NTAG * NTAG)        trans = (const float*)d_in[i];
    }
    crf_prep<<<40, 256>>>(trans, maskp);
    crf_main<<<BATCH, 32>>>(feats, trans, (float*)d_out);
}